// round 5
// baseline (speedup 1.0000x reference)
#include <cuda_runtime.h>
#include <cuda_bf16.h>

// Problem constants: IN=4, H=30, OUT=1, N_UNIT=100, B=262144
#define NU    100
#define HH    30
#define NT    256          // threads per block
#define RPT   2            // rows per thread
#define RPB   (NT * RPT)   // 512 rows per block

typedef unsigned long long u64;

// ---- packed f32x2 helpers (sm_103a) ----
__device__ __forceinline__ u64 ffma2(u64 a, u64 b, u64 c) {
    u64 d;
    asm("fma.rn.f32x2 %0, %1, %2, %3;" : "=l"(d) : "l"(a), "l"(b), "l"(c));
    return d;
}
__device__ __forceinline__ u64 pack2(float x, float y) {
    u64 d;
    asm("mov.b64 %0, {%1, %2};" : "=l"(d) : "f"(x), "f"(y));
    return d;
}
__device__ __forceinline__ float2 unpack2(u64 a) {
    float2 f;
    asm("mov.b64 {%0, %1}, %2;" : "=f"(f.x), "=f"(f.y) : "l"(a));
    return f;
}
__device__ __forceinline__ u64 relu2(u64 a) {
    float2 f = unpack2(a);
    return pack2(fmaxf(f.x, 0.0f), fmaxf(f.y, 0.0f));
}

// ---------------------------------------------------------------------------
// Single fused kernel: per-block merit-order setup (redundant, deterministic),
// packed-f32x2 MLP (2 rows/thread), coalesced float4 tile stores.
// __launch_bounds__(256,3) -> 85-reg budget -> 3 blocks/SM.
// ---------------------------------------------------------------------------
__global__ __launch_bounds__(NT, 3)
void mlp_dispatch_kernel(const float4* __restrict__ x,     // [B,4] as float4
                         const float*  __restrict__ Cost,  // [100]
                         const float*  __restrict__ Pmax,  // [100]
                         const float*  __restrict__ Pd,    // [100]
                         const float*  __restrict__ wcap,  // [1]
                         const float*  __restrict__ W1,    // [4,30]
                         const float*  __restrict__ b1,    // [30]
                         const float*  __restrict__ W2,    // [30,30]
                         const float*  __restrict__ b2,    // [30]
                         const float*  __restrict__ W3,    // [30,1]
                         const float*  __restrict__ b3,    // [1]
                         float*        __restrict__ out)   // [B,100]
{
    // duplicated-weight shared arrays: element i holds (w,w)
    __shared__ alignas(16) u64 sW1d[4 * HH];
    __shared__ alignas(16) u64 sW2d[HH * HH];
    __shared__ alignas(16) u64 sb1d[HH];
    __shared__ alignas(16) u64 sb2d[HH];
    __shared__ alignas(16) u64 sW3d[HH];
    __shared__ alignas(16) float sCost[NU];
    __shared__ alignas(16) float sCum[NU];
    __shared__ alignas(16) float sPmax[NU];
    __shared__ alignas(16) float sTd[RPB];
    __shared__ float sB3, sWc, sSum;

    const int tid = threadIdx.x;

    // ---- Stage params ----
    for (int i = tid; i < 4 * HH; i += NT)  { float w = W1[i]; sW1d[i] = pack2(w, w); }
    for (int i = tid; i < HH * HH; i += NT) { float w = W2[i]; sW2d[i] = pack2(w, w); }
    if (tid < HH) {
        float v1 = b1[tid]; sb1d[tid] = pack2(v1, v1);
        float v2 = b2[tid]; sb2d[tid] = pack2(v2, v2);
        float v3 = W3[tid]; sW3d[tid] = pack2(v3, v3);
    }
    if (tid < NU) { sCost[tid] = Cost[tid]; sPmax[tid] = Pmax[tid]; }
    if (tid == 0) { sB3 = b3[0]; sWc = wcap[0]; }
    // parallel sum(Pd) by warp 0
    if (tid < 32) {
        float s = 0.0f;
        for (int j = tid; j < NU; j += 32) s += Pd[j];
        #pragma unroll
        for (int o = 16; o > 0; o >>= 1)
            s += __shfl_xor_sync(0xFFFFFFFFu, s, o);
        if (tid == 0) sSum = s;
    }
    __syncthreads();

    // ---- Merit order (stable argsort closed form), per original unit ----
    // cum_prev[j] = sum_k Pmax[k] where Cost[k]<Cost[j] || (==, k<j)
    if (tid < NU) {
        const float cj = sCost[tid];
        float cum = 0.0f;
        #pragma unroll 4
        for (int k = 0; k < NU; k++) {
            float ck = sCost[k];
            bool cheaper = (ck < cj) || (ck == cj && k < tid);
            if (cheaper) cum += sPmax[k];
        }
        sCum[tid] = cum;
    }

    // ---- load this thread's 2 rows of x, transpose into packed lanes ----
    const long row0 = ((long)blockIdx.x * NT + tid) * RPT;
    const float4 x0 = x[row0];
    const float4 x1 = x[row0 + 1];
    const u64 xp0 = pack2(x0.x, x1.x);
    const u64 xp1 = pack2(x0.y, x1.y);
    const u64 xp2 = pack2(x0.z, x1.z);
    const u64 xp3 = pack2(x0.w, x1.w);

    __syncthreads();   // params + merit order ready

    // ---- layer 2 accumulators (packed pair per hidden unit) ----
    u64 h2p[HH];
    #pragma unroll
    for (int k = 0; k < HH; k++) h2p[k] = sb2d[k];

    // ---- h1 in chunks of 5 to bound live registers (85-reg budget) ----
    #pragma unroll
    for (int c = 0; c < 6; c++) {
        u64 h1p[5];
        #pragma unroll
        for (int ii = 0; ii < 5; ii++) {
            const int i = c * 5 + ii;
            u64 a = sb1d[i];
            a = ffma2(xp0, sW1d[0 * HH + i], a);
            a = ffma2(xp1, sW1d[1 * HH + i], a);
            a = ffma2(xp2, sW1d[2 * HH + i], a);
            a = ffma2(xp3, sW1d[3 * HH + i], a);
            h1p[ii] = relu2(a);
        }
        #pragma unroll
        for (int ii = 0; ii < 5; ii++) {
            const int i = c * 5 + ii;
            const u64 h = h1p[ii];
            #pragma unroll
            for (int k = 0; k < HH; k += 2) {
                ulonglong2 w = *reinterpret_cast<const ulonglong2*>(&sW2d[i * HH + k]);
                h2p[k]     = ffma2(h, w.x, h2p[k]);
                h2p[k + 1] = ffma2(h, w.y, h2p[k + 1]);
            }
        }
    }

    // ---- output layer ----
    u64 yp = pack2(sB3, sB3);
    #pragma unroll
    for (int i = 0; i < HH; i++)
        yp = ffma2(relu2(h2p[i]), sW3d[i], yp);
    const float2 yv = unpack2(yp);

    sTd[tid * RPT]     = sSum - sWc * yv.x;
    sTd[tid * RPT + 1] = sSum - sWc * yv.y;
    __syncthreads();

    // ---- coalesced tile store: RPB rows x 100 units = RPB*25 float4 ----
    float4* outv = reinterpret_cast<float4*>(out + (size_t)blockIdx.x * RPB * NU);
    #pragma unroll
    for (int it = 0; it < (RPB * NU / 4) / NT; it++) {   // 50 iterations
        int i = tid + it * NT;          // linear float4 index within tile
        int r = i / 25;                 // row within tile (25 vec4 per row)
        int g = i - r * 25;             // vec4 group within row
        float t = sTd[r];
        float4 cu = *reinterpret_cast<const float4*>(sCum  + 4 * g);
        float4 pm = *reinterpret_cast<const float4*>(sPmax + 4 * g);
        float4 p;
        p.x = fminf(fmaxf(t - cu.x, 0.0f), pm.x);
        p.y = fminf(fmaxf(t - cu.y, 0.0f), pm.y);
        p.z = fminf(fmaxf(t - cu.z, 0.0f), pm.z);
        p.w = fminf(fmaxf(t - cu.w, 0.0f), pm.w);
        outv[i] = p;
    }
}

// ---------------------------------------------------------------------------
// Launch. Input order: x, Cost, Pmax, Pd, w_capacity, W1, b1, W2, b2, W3, b3
// ---------------------------------------------------------------------------
extern "C" void kernel_launch(void* const* d_in, const int* in_sizes, int n_in,
                              void* d_out, int out_size) {
    const float* x     = (const float*)d_in[0];
    const float* Cost  = (const float*)d_in[1];
    const float* Pmax  = (const float*)d_in[2];
    const float* Pd    = (const float*)d_in[3];
    const float* wcap  = (const float*)d_in[4];
    const float* W1    = (const float*)d_in[5];
    const float* b1    = (const float*)d_in[6];
    const float* W2    = (const float*)d_in[7];
    const float* b2    = (const float*)d_in[8];
    const float* W3    = (const float*)d_in[9];
    const float* b3    = (const float*)d_in[10];
    float* out = (float*)d_out;

    const int B = in_sizes[0] / 4;      // x is [B, 4]
    const int blocks = B / RPB;         // 262144 / 512 = 512

    mlp_dispatch_kernel<<<blocks, NT>>>(
        (const float4*)x, Cost, Pmax, Pd, wcap, W1, b1, W2, b2, W3, b3, out);
}

// round 6
// speedup vs baseline: 2.0078x; 2.0078x over previous
#include <cuda_runtime.h>
#include <cuda_bf16.h>

// Problem constants: IN=4, H=30, OUT=1, N_UNIT=100, B=262144
#define NU    100
#define HH    30
#define NT    256          // threads per block
#define RPT   2            // rows per thread
#define RPB   (NT * RPT)   // 512 rows per block
#define KP    (HH / 2)     // 15 packed k-pairs

typedef unsigned long long u64;

// ---- packed f32x2 helpers (sm_103a) ----
__device__ __forceinline__ u64 ffma2(u64 a, u64 b, u64 c) {
    u64 d;
    asm("fma.rn.f32x2 %0, %1, %2, %3;" : "=l"(d) : "l"(a), "l"(b), "l"(c));
    return d;
}
__device__ __forceinline__ u64 pack2(float x, float y) {
    u64 d;
    asm("mov.b64 %0, {%1, %2};" : "=l"(d) : "f"(x), "f"(y));
    return d;
}
__device__ __forceinline__ float2 unpack2(u64 a) {
    float2 f;
    asm("mov.b64 {%0, %1}, %2;" : "=f"(f.x), "=f"(f.y) : "l"(a));
    return f;
}
__device__ __forceinline__ u64 relu2(u64 a) {
    float2 f = unpack2(a);
    return pack2(fmaxf(f.x, 0.0f), fmaxf(f.y, 0.0f));
}

// ---------------------------------------------------------------------------
// Fused kernel: per-block merit-order setup, k-packed f32x2 MLP
// (2 rows/thread, unduplicated W2), coalesced float4 tile stores.
// ---------------------------------------------------------------------------
__global__ __launch_bounds__(NT, 2)
void mlp_dispatch_kernel(const float4* __restrict__ x,     // [B,4] as float4
                         const float*  __restrict__ Cost,  // [100]
                         const float*  __restrict__ Pmax,  // [100]
                         const float*  __restrict__ Pd,    // [100]
                         const float*  __restrict__ wcap,  // [1]
                         const float*  __restrict__ W1,    // [4,30]
                         const float*  __restrict__ b1,    // [30]
                         const float*  __restrict__ W2,    // [30,30]
                         const float*  __restrict__ b2,    // [30]
                         const float*  __restrict__ W3,    // [30,1]
                         const float*  __restrict__ b3,    // [1]
                         float*        __restrict__ out)   // [B,100]
{
    __shared__ alignas(16) u64   sW1d[4 * HH];   // W1 duplicated (row-packed layer 1)
    __shared__ alignas(16) u64   sb1d[HH];       // b1 duplicated
    __shared__ alignas(16) float sW2[HH * 32];   // W2 rows padded to 32 floats (128B)
    __shared__ alignas(16) float sb2[HH];        // unduplicated (k-pair loads)
    __shared__ alignas(16) float sW3[HH];        // unduplicated (k-pair loads)
    __shared__ alignas(16) float sCost[NU];
    __shared__ alignas(16) float sCum[NU];
    __shared__ alignas(16) float sPmax[NU];
    __shared__ alignas(16) float sTd[RPB];
    __shared__ float sB3, sWc, sSum;

    const int tid = threadIdx.x;

    // ---- Stage params ----
    for (int i = tid; i < 4 * HH; i += NT) { float w = W1[i]; sW1d[i] = pack2(w, w); }
    for (int i = tid; i < HH * 32; i += NT) {
        int r = i >> 5, c = i & 31;
        sW2[i] = (c < HH) ? W2[r * HH + c] : 0.0f;
    }
    if (tid < HH) {
        float v1 = b1[tid]; sb1d[tid] = pack2(v1, v1);
        sb2[tid] = b2[tid];
        sW3[tid] = W3[tid];
    }
    if (tid < NU) { sCost[tid] = Cost[tid]; sPmax[tid] = Pmax[tid]; }
    if (tid == 0) { sB3 = b3[0]; sWc = wcap[0]; }
    // parallel sum(Pd) by warp 0
    if (tid < 32) {
        float s = 0.0f;
        for (int j = tid; j < NU; j += 32) s += Pd[j];
        #pragma unroll
        for (int o = 16; o > 0; o >>= 1)
            s += __shfl_xor_sync(0xFFFFFFFFu, s, o);
        if (tid == 0) sSum = s;
    }
    __syncthreads();

    // ---- Merit order (stable argsort closed form), per original unit ----
    if (tid < NU) {
        const float cj = sCost[tid];
        float cum = 0.0f;
        #pragma unroll 4
        for (int k = 0; k < NU; k++) {
            float ck = sCost[k];
            bool cheaper = (ck < cj) || (ck == cj && k < tid);
            if (cheaper) cum += sPmax[k];
        }
        sCum[tid] = cum;
    }

    // ---- load this thread's 2 rows of x ----
    const long row0 = ((long)blockIdx.x * NT + tid) * RPT;
    const float4 x0 = x[row0];
    const float4 x1 = x[row0 + 1];
    const u64 xp0 = pack2(x0.x, x1.x);   // (row0, row1) packed per input feature
    const u64 xp1 = pack2(x0.y, x1.y);
    const u64 xp2 = pack2(x0.z, x1.z);
    const u64 xp3 = pack2(x0.w, x1.w);

    __syncthreads();

    // ---- layer-2 accumulators, k-packed: accR[kp] = (h2[2kp], h2[2kp+1]) of row R
    u64 acc0[KP], acc1[KP];
    #pragma unroll
    for (int kp = 0; kp < KP; kp++) {
        u64 bp = *reinterpret_cast<const u64*>(&sb2[2 * kp]);
        acc0[kp] = bp;
        acc1[kp] = bp;
    }

    // ---- fused layer1 + layer2: one hidden unit i at a time ----
    #pragma unroll
    for (int i = 0; i < HH; i++) {
        // layer-1 unit i, rows packed
        u64 a = sb1d[i];
        a = ffma2(xp0, sW1d[0 * HH + i], a);
        a = ffma2(xp1, sW1d[1 * HH + i], a);
        a = ffma2(xp2, sW1d[2 * HH + i], a);
        a = ffma2(xp3, sW1d[3 * HH + i], a);
        const float2 h = unpack2(relu2(a));
        const u64 h0d = pack2(h.x, h.x);     // row0 broadcast
        const u64 h1d = pack2(h.y, h.y);     // row1 broadcast

        // accumulate row i of W2 (unduplicated, float4 = 2 k-pairs per LDS.128)
        const float* wrow = &sW2[i * 32];
        #pragma unroll
        for (int q = 0; q < 7; q++) {        // k-pairs 0..13
            ulonglong2 wv = *reinterpret_cast<const ulonglong2*>(wrow + 4 * q);
            acc0[2 * q]     = ffma2(h0d, wv.x, acc0[2 * q]);
            acc1[2 * q]     = ffma2(h1d, wv.x, acc1[2 * q]);
            acc0[2 * q + 1] = ffma2(h0d, wv.y, acc0[2 * q + 1]);
            acc1[2 * q + 1] = ffma2(h1d, wv.y, acc1[2 * q + 1]);
        }
        {                                     // k-pair 14
            u64 wv = *reinterpret_cast<const u64*>(wrow + 28);
            acc0[14] = ffma2(h0d, wv, acc0[14]);
            acc1[14] = ffma2(h1d, wv, acc1[14]);
        }
    }

    // ---- output layer: y_r = b3 + sum_k relu(h2_r[k]) * W3[k] ----
    u64 yp0 = pack2(sB3, 0.0f);
    u64 yp1 = pack2(sB3, 0.0f);
    #pragma unroll
    for (int kp = 0; kp < KP; kp++) {
        u64 w3p = *reinterpret_cast<const u64*>(&sW3[2 * kp]);
        yp0 = ffma2(relu2(acc0[kp]), w3p, yp0);
        yp1 = ffma2(relu2(acc1[kp]), w3p, yp1);
    }
    const float2 y0 = unpack2(yp0);
    const float2 y1 = unpack2(yp1);

    sTd[tid * RPT]     = sSum - sWc * (y0.x + y0.y);
    sTd[tid * RPT + 1] = sSum - sWc * (y1.x + y1.y);
    __syncthreads();

    // ---- coalesced tile store: RPB rows x 100 units = RPB*25 float4 ----
    float4* outv = reinterpret_cast<float4*>(out + (size_t)blockIdx.x * RPB * NU);
    #pragma unroll
    for (int it = 0; it < (RPB * NU / 4) / NT; it++) {   // 50 iterations
        int i = tid + it * NT;          // linear float4 index within tile
        int r = i / 25;                 // row within tile (25 vec4 per row)
        int g = i - r * 25;             // vec4 group within row
        float t = sTd[r];
        float4 cu = *reinterpret_cast<const float4*>(sCum  + 4 * g);
        float4 pm = *reinterpret_cast<const float4*>(sPmax + 4 * g);
        float4 p;
        p.x = fminf(fmaxf(t - cu.x, 0.0f), pm.x);
        p.y = fminf(fmaxf(t - cu.y, 0.0f), pm.y);
        p.z = fminf(fmaxf(t - cu.z, 0.0f), pm.z);
        p.w = fminf(fmaxf(t - cu.w, 0.0f), pm.w);
        outv[i] = p;
    }
}

// ---------------------------------------------------------------------------
// Launch. Input order: x, Cost, Pmax, Pd, w_capacity, W1, b1, W2, b2, W3, b3
// ---------------------------------------------------------------------------
extern "C" void kernel_launch(void* const* d_in, const int* in_sizes, int n_in,
                              void* d_out, int out_size) {
    const float* x     = (const float*)d_in[0];
    const float* Cost  = (const float*)d_in[1];
    const float* Pmax  = (const float*)d_in[2];
    const float* Pd    = (const float*)d_in[3];
    const float* wcap  = (const float*)d_in[4];
    const float* W1    = (const float*)d_in[5];
    const float* b1    = (const float*)d_in[6];
    const float* W2    = (const float*)d_in[7];
    const float* b2    = (const float*)d_in[8];
    const float* W3    = (const float*)d_in[9];
    const float* b3    = (const float*)d_in[10];
    float* out = (float*)d_out;

    const int B = in_sizes[0] / 4;      // x is [B, 4]
    const int blocks = B / RPB;         // 262144 / 512 = 512

    mlp_dispatch_kernel<<<blocks, NT>>>(
        (const float4*)x, Cost, Pmax, Pd, wcap, W1, b1, W2, b2, W3, b3, out);
}